// round 1
// baseline (speedup 1.0000x reference)
#include <cuda_runtime.h>
#include <math.h>
#include <stdint.h>

// Problem constants (fixed by setup_inputs)
#define V_  100000
#define E_  256
#define H_  256
#define B_  256
#define S_  10
#define TC_ 20
#define TS_ 50
#define BC_ (B_ * S_)   // 2560
#define H3_ (3 * H_)    // 768

// ---------------- scratch (static device globals; no allocation) ----------------
__device__ float g_gi_c[(size_t)BC_ * TC_ * H3_];  // 39.3M floats
__device__ float g_gi_s[(size_t)B_ * TS_ * H3_];   // 9.8M floats
__device__ float g_hA[BC_ * H_];
__device__ float g_hB[BC_ * H_];
__device__ float g_hsA[B_ * H_];
__device__ float g_hsB[B_ * H_];
__device__ float g_seq_cate[BC_ * H_];
__device__ float g_out_short[B_ * H_];
__device__ float g_sum_cate[B_ * H_];
__device__ float g_fc_out[B_ * H_];

// ---------------- NT GEMM: C[m,n] = sum_k Arow(m)[k] * Bm[n,k] (+bias[n]) ------
// Arow(m) = A + (idx ? idx[m] : m) * K   (fused embedding gather)
// Tiling: 128x128x8, 256 threads, 8x8 per thread. M must be a multiple of 128.
__global__ void __launch_bounds__(256) gemm_nt_128(
    const float* __restrict__ A, const int* __restrict__ idx,
    const float* __restrict__ Bm, const float* __restrict__ bias,
    float* __restrict__ C, int M, int N, int K)
{
    __shared__ float As[8][128];
    __shared__ float Bs[8][128];
    const int tid = threadIdx.x;
    const int bm = blockIdx.x * 128;
    const int bn = blockIdx.y * 128;
    const int lr = tid >> 1;            // 0..127 tile row for loading
    const int lk = (tid & 1) * 4;       // 0 or 4
    const int tx = tid & 15;            // n-group
    const int ty = tid >> 4;            // m-group
    const int tm0 = ty * 8, tn0 = tx * 8;

    const int am = bm + lr;
    const float* arow = A + (size_t)(idx ? idx[am] : am) * K;
    const int brow = bn + lr;
    const float* brp = Bm + (size_t)brow * K;
    const bool bvalid = (brow < N);

    float acc[8][8];
#pragma unroll
    for (int i = 0; i < 8; i++)
#pragma unroll
        for (int j = 0; j < 8; j++) acc[i][j] = 0.f;

    for (int k0 = 0; k0 < K; k0 += 8) {
        float4 av = *(const float4*)(arow + k0 + lk);
        float4 bv = bvalid ? *(const float4*)(brp + k0 + lk)
                           : make_float4(0.f, 0.f, 0.f, 0.f);
        As[lk + 0][lr] = av.x; As[lk + 1][lr] = av.y;
        As[lk + 2][lr] = av.z; As[lk + 3][lr] = av.w;
        Bs[lk + 0][lr] = bv.x; Bs[lk + 1][lr] = bv.y;
        Bs[lk + 2][lr] = bv.z; Bs[lk + 3][lr] = bv.w;
        __syncthreads();
#pragma unroll
        for (int k = 0; k < 8; k++) {
            float4 a0 = *(const float4*)&As[k][tm0];
            float4 a1 = *(const float4*)&As[k][tm0 + 4];
            float4 b0 = *(const float4*)&Bs[k][tn0];
            float4 b1 = *(const float4*)&Bs[k][tn0 + 4];
            float am8[8] = {a0.x, a0.y, a0.z, a0.w, a1.x, a1.y, a1.z, a1.w};
            float bn8[8] = {b0.x, b0.y, b0.z, b0.w, b1.x, b1.y, b1.z, b1.w};
#pragma unroll
            for (int i = 0; i < 8; i++)
#pragma unroll
                for (int j = 0; j < 8; j++) acc[i][j] += am8[i] * bn8[j];
        }
        __syncthreads();
    }

#pragma unroll
    for (int i = 0; i < 8; i++) {
        const int m = bm + tm0 + i;
        float* crow = C + (size_t)m * N;
#pragma unroll
        for (int j = 0; j < 8; j++) {
            const int n = bn + tn0 + j;
            if (n < N) crow[n] = acc[i][j] + (bias ? bias[n] : 0.f);
        }
    }
}

// ---------------- fused GRU step: gh = h@Whh^T, gate math, h update -----------
// grid (Mrows/64, H/64), 256 threads. 64 rows x 64 j per block, 3 gates fused.
// Writes gathered[b,:] = h_new * mask[b,t] when t == slen[b].
__global__ void __launch_bounds__(256) gru_step_kernel(
    const float* __restrict__ Whh, const float* __restrict__ bhh,
    const float* __restrict__ gi,  const float* __restrict__ h_in,
    float* __restrict__ h_out,     const int* __restrict__ slen,
    const float* __restrict__ mask, float* __restrict__ gathered,
    int t, int T)
{
    __shared__ float Hs[16][64];
    __shared__ float Ws[3][16][64];
    const int tid = threadIdx.x;
    const int bm = blockIdx.x * 64;
    const int bj = blockIdx.y * 64;
    const int lr = tid >> 2;           // 0..63
    const int lk = (tid & 3) * 4;      // 0,4,8,12
    const int tx = tid & 15, ty = tid >> 4;
    const int tm0 = ty * 4, tn0 = tx * 4;

    float ar[4][4] = {}, az[4][4] = {}, an[4][4] = {};

    if (t > 0) {
        const float* hrow = h_in + (size_t)(bm + lr) * H_;
        const float* w0 = Whh + (size_t)(0 * H_ + bj + lr) * H_;
        const float* w1 = Whh + (size_t)(1 * H_ + bj + lr) * H_;
        const float* w2 = Whh + (size_t)(2 * H_ + bj + lr) * H_;
        for (int k0 = 0; k0 < H_; k0 += 16) {
            float4 hv = *(const float4*)(hrow + k0 + lk);
            float4 v0 = *(const float4*)(w0 + k0 + lk);
            float4 v1 = *(const float4*)(w1 + k0 + lk);
            float4 v2 = *(const float4*)(w2 + k0 + lk);
            Hs[lk + 0][lr] = hv.x; Hs[lk + 1][lr] = hv.y;
            Hs[lk + 2][lr] = hv.z; Hs[lk + 3][lr] = hv.w;
            Ws[0][lk + 0][lr] = v0.x; Ws[0][lk + 1][lr] = v0.y;
            Ws[0][lk + 2][lr] = v0.z; Ws[0][lk + 3][lr] = v0.w;
            Ws[1][lk + 0][lr] = v1.x; Ws[1][lk + 1][lr] = v1.y;
            Ws[1][lk + 2][lr] = v1.z; Ws[1][lk + 3][lr] = v1.w;
            Ws[2][lk + 0][lr] = v2.x; Ws[2][lk + 1][lr] = v2.y;
            Ws[2][lk + 2][lr] = v2.z; Ws[2][lk + 3][lr] = v2.w;
            __syncthreads();
#pragma unroll
            for (int k = 0; k < 16; k++) {
                float4 h4 = *(const float4*)&Hs[k][tm0];
                float4 r4 = *(const float4*)&Ws[0][k][tn0];
                float4 z4 = *(const float4*)&Ws[1][k][tn0];
                float4 n4 = *(const float4*)&Ws[2][k][tn0];
                float hm[4] = {h4.x, h4.y, h4.z, h4.w};
                float rr[4] = {r4.x, r4.y, r4.z, r4.w};
                float zz[4] = {z4.x, z4.y, z4.z, z4.w};
                float nn[4] = {n4.x, n4.y, n4.z, n4.w};
#pragma unroll
                for (int i = 0; i < 4; i++)
#pragma unroll
                    for (int j = 0; j < 4; j++) {
                        ar[i][j] += hm[i] * rr[j];
                        az[i][j] += hm[i] * zz[j];
                        an[i][j] += hm[i] * nn[j];
                    }
            }
            __syncthreads();
        }
    }

#pragma unroll
    for (int i = 0; i < 4; i++) {
        const int b = bm + tm0 + i;
        const float* girow = gi + ((size_t)b * T + t) * H3_;
        const bool take = (slen[b] == t);
        const float mval = mask[(size_t)b * T + t];
#pragma unroll
        for (int j = 0; j < 4; j++) {
            const int jj = bj + tn0 + j;
            const float gr = girow[jj];
            const float gz = girow[H_ + jj];
            const float gn = girow[2 * H_ + jj];
            const float hr = ar[i][j] + bhh[jj];
            const float hz = az[i][j] + bhh[H_ + jj];
            const float hn = an[i][j] + bhh[2 * H_ + jj];
            const float hold = (t > 0) ? h_in[(size_t)b * H_ + jj] : 0.f;
            const float r = 1.f / (1.f + expf(-(gr + hr)));
            const float z = 1.f / (1.f + expf(-(gz + hz)));
            const float n = tanhf(gn + r * hn);
            const float hnew = (1.f - z) * n + z * hold;
            h_out[(size_t)b * H_ + jj] = hnew;
            if (take) gathered[(size_t)b * H_ + jj] = hnew * mval;
        }
    }
}

// ---------------- attention: masked softmax of out_short over seq_cate -------
__global__ void attention_kernel(const float* __restrict__ seq_cate,
                                 const float* __restrict__ out_short,
                                 const float* __restrict__ mask_seq,
                                 float* __restrict__ sum_cate)
{
    const int b = blockIdx.x;
    const int j = threadIdx.x;  // 256 = H
    __shared__ float red[8];
    __shared__ float w[S_];
    const float os = out_short[(size_t)b * H_ + j];
    float sc[S_];
#pragma unroll
    for (int s = 0; s < S_; s++)
        sc[s] = seq_cate[(size_t)(b * S_ + s) * H_ + j];

    for (int s = 0; s < S_; s++) {
        float v = sc[s] * os;
#pragma unroll
        for (int off = 16; off; off >>= 1) v += __shfl_xor_sync(0xffffffffu, v, off);
        if ((j & 31) == 0) red[j >> 5] = v;
        __syncthreads();
        if (j == 0) {
            float x = 0.f;
#pragma unroll
            for (int q = 0; q < 8; q++) x += red[q];
            w[s] = x;
        }
        __syncthreads();
    }
    if (j == 0) {
        float mx = w[0];
        for (int s = 1; s < S_; s++) mx = fmaxf(mx, w[s]);
        float e[S_];
        float sum = 0.f;
        for (int s = 0; s < S_; s++) { e[s] = expf(w[s] - mx); sum += e[s]; }
        float s2 = 0.f;
        for (int s = 0; s < S_; s++) {
            e[s] = (e[s] / sum) * mask_seq[(size_t)b * S_ + s];
            s2 += e[s];
        }
        for (int s = 0; s < S_; s++) w[s] = e[s] / s2;
    }
    __syncthreads();
    float acc = 0.f;
#pragma unroll
    for (int s = 0; s < S_; s++) acc += w[s] * sc[s];
    sum_cate[(size_t)b * H_ + j] = acc;
}

// ---------------- FC: fc_out[b,i] = [sum_cate|out_short][b,:] . fc_W[i,:] ----
__global__ void fc_kernel(const float* __restrict__ sum_cate,
                          const float* __restrict__ out_short,
                          const float* __restrict__ fcW,
                          const float* __restrict__ fcb,
                          float* __restrict__ fc_out)
{
    __shared__ float mix[16][2 * H_];
    const int b0 = blockIdx.x * 16;
    for (int idx = threadIdx.x; idx < 16 * 2 * H_; idx += 256) {
        const int bb = idx >> 9, k = idx & 511;
        mix[bb][k] = (k < H_) ? sum_cate[(size_t)(b0 + bb) * H_ + k]
                              : out_short[(size_t)(b0 + bb) * H_ + (k - H_)];
    }
    __syncthreads();
    const int i = threadIdx.x;
    const float* wrow = fcW + (size_t)i * (2 * H_);
    float acc[16];
#pragma unroll
    for (int bb = 0; bb < 16; bb++) acc[bb] = 0.f;
    for (int k = 0; k < 2 * H_; k++) {
        const float wv = wrow[k];
#pragma unroll
        for (int bb = 0; bb < 16; bb++) acc[bb] += wv * mix[bb][k];
    }
    const float bias = fcb[i];
#pragma unroll
    for (int bb = 0; bb < 16; bb++)
        fc_out[(size_t)(b0 + bb) * H_ + i] = acc[bb] + bias;
}

__global__ void write_targets(const int* __restrict__ tgt, float* __restrict__ out)
{
    const int i = threadIdx.x;
    out[i] = (float)tgt[i];
}

// ---------------- launcher ----------------------------------------------------
extern "C" void kernel_launch(void* const* d_in, const int* in_sizes, int n_in,
                              void* d_out, int out_size)
{
    const int*   in_cate       = (const int*)d_in[0];
    const float* mask_cate     = (const float*)d_in[1];
    const float* mask_cate_seq = (const float*)d_in[2];
    const int*   subseqLen     = (const int*)d_in[5];
    const int*   in_batch      = (const int*)d_in[7];
    const float* mask_b        = (const float*)d_in[8];
    const int*   seqLen        = (const int*)d_in[9];
    const int*   target        = (const int*)d_in[10];
    const float* emb           = (const float*)d_in[12];
    const float* Wih_c         = (const float*)d_in[13];
    const float* Whh_c         = (const float*)d_in[14];
    const float* bih_c         = (const float*)d_in[15];
    const float* bhh_c         = (const float*)d_in[16];
    const float* Wih_s         = (const float*)d_in[17];
    const float* Whh_s         = (const float*)d_in[18];
    const float* bih_s         = (const float*)d_in[19];
    const float* bhh_s         = (const float*)d_in[20];
    const float* fc_W          = (const float*)d_in[21];
    const float* fc_b          = (const float*)d_in[22];
    float* out = (float*)d_out;

    float *gi_c, *gi_s, *hA, *hB, *hsA, *hsB, *seqc, *osht, *sumc, *fco;
    cudaGetSymbolAddress((void**)&gi_c, g_gi_c);
    cudaGetSymbolAddress((void**)&gi_s, g_gi_s);
    cudaGetSymbolAddress((void**)&hA,  g_hA);
    cudaGetSymbolAddress((void**)&hB,  g_hB);
    cudaGetSymbolAddress((void**)&hsA, g_hsA);
    cudaGetSymbolAddress((void**)&hsB, g_hsB);
    cudaGetSymbolAddress((void**)&seqc, g_seq_cate);
    cudaGetSymbolAddress((void**)&osht, g_out_short);
    cudaGetSymbolAddress((void**)&sumc, g_sum_cate);
    cudaGetSymbolAddress((void**)&fco,  g_fc_out);

    // 1) input-gate GEMMs (fused embedding gather)
    gemm_nt_128<<<dim3(BC_ * TC_ / 128, H3_ / 128), 256>>>(
        emb, in_cate, Wih_c, bih_c, gi_c, BC_ * TC_, H3_, E_);
    gemm_nt_128<<<dim3(B_ * TS_ / 128, H3_ / 128), 256>>>(
        emb, in_batch, Wih_s, bih_s, gi_s, B_ * TS_, H3_, E_);

    // 2) category GRU scan (ping-pong h)
    {
        float* hin = hA; float* hout = hB;
        for (int t = 0; t < TC_; t++) {
            gru_step_kernel<<<dim3(BC_ / 64, H_ / 64), 256>>>(
                Whh_c, bhh_c, gi_c, hin, hout, subseqLen, mask_cate, seqc, t, TC_);
            float* tmp = hin; hin = hout; hout = tmp;
        }
    }
    // 3) short GRU scan
    {
        float* hin = hsA; float* hout = hsB;
        for (int t = 0; t < TS_; t++) {
            gru_step_kernel<<<dim3(B_ / 64, H_ / 64), 256>>>(
                Whh_s, bhh_s, gi_s, hin, hout, seqLen, mask_b, osht, t, TS_);
            float* tmp = hin; hin = hout; hout = tmp;
        }
    }
    // 4) attention + 5) FC
    attention_kernel<<<B_, 256>>>(seqc, osht, mask_cate_seq, sumc);
    fc_kernel<<<B_ / 16, 256>>>(sumc, osht, fc_W, fc_b, fco);

    // 6) logits = fc_out @ emb^T
    gemm_nt_128<<<dim3(B_ / 128, (V_ + 127) / 128), 256>>>(
        fco, nullptr, emb, nullptr, out, B_, V_, H_);

    // 7) targets appended as float, if the output carries them
    if (out_size >= B_ * V_ + B_)
        write_targets<<<1, B_>>>(target, out + (size_t)B_ * V_);
}